// round 3
// baseline (speedup 1.0000x reference)
#include <cuda_runtime.h>
#include <math.h>

#define Bb 64
#define Cc 8
#define Nn 2048
#define Tt 64
#define NSPLIT 8
#define BPG 16                              // batches per group: x[g] = 64 MB < L2
#define GROUPS (Bb / BPG)                   // 4
#define RED_BLOCKS (BPG * Cc * NSPLIT)      // 1024
#define AGG_BLOCKS (BPG * 128)              // 2048
#define NT4 (Nn * Tt / 4)                   // 32768 float4 per (b,c)

// atomic-free reduction partials: [b*Cc+c][split][t]  (1 MB)
__device__ float g_part[Bb * Cc * NSPLIT * Tt];

// ---------------------------------------------------------------------------
// Phase 1: k partials for group g. Pure DRAM read stream; plants x[g] in L2.
// 1024 blocks x 256 threads. Block = one (b,c,split): 256 n-rows.
// ---------------------------------------------------------------------------
__global__ void __launch_bounds__(256)
k_reduce(const float* __restrict__ x, const float* __restrict__ alpha, int g) {
    int r     = blockIdx.x;
    int bcl   = r >> 3;                     // 0..127  (local b*8 + c)
    int split = r & 7;
    int b     = g * BPG + (bcl >> 3);
    int c     = bcl & 7;
    const float* xp = x + ((long)(b * Cc + c)) * Nn * Tt;

    __shared__ float s_alpha[256];
    __shared__ float4 s_red[256];

    int tid = threadIdx.x;
    s_alpha[tid] = alpha[split * 256 + tid];
    __syncthreads();

    int t4 = tid & 15, row = tid >> 4;
    int nbase = split * 256;
    float4 acc = make_float4(0.f, 0.f, 0.f, 0.f);
    #pragma unroll
    for (int i = 0; i < 16; i++) {
        int nl = row + i * 16;
        float4 v = reinterpret_cast<const float4*>(xp + (long)(nbase + nl) * Tt)[t4];
        float a = s_alpha[nl];
        acc.x += v.x * a; acc.y += v.y * a;
        acc.z += v.z * a; acc.w += v.w * a;
    }

    s_red[tid] = acc;
    __syncthreads();
    #pragma unroll
    for (int off = 8; off >= 1; off >>= 1) {
        if (row < off) {
            float4 o = s_red[(row + off) * 16 + t4];
            acc.x += o.x; acc.y += o.y; acc.z += o.z; acc.w += o.w;
            s_red[tid] = acc;
        }
        __syncthreads();
    }
    if (row == 0)
        reinterpret_cast<float4*>(
            g_part + ((long)(b * Cc + c) * NSPLIT + split) * Tt)[t4] = acc;
}

// ---------------------------------------------------------------------------
// Phase 2: aggregate group g. x[g] read from L2 (evict-first), out streamed.
// 2048 blocks x 256 threads. att[b] recomputed per block (cheap, hidden).
// ---------------------------------------------------------------------------
__global__ void __launch_bounds__(256)
k_agg(const float* __restrict__ x, const float* __restrict__ Wc,
      float* __restrict__ out, int g) {
    int bl    = blockIdx.x >> 7;            // 0..15
    int chunk = blockIdx.x & 127;
    int b     = g * BPG + bl;
    int tid   = threadIdx.x;

    __shared__ float sW[64 * 64];
    __shared__ float sk[8 * 64];
    __shared__ float sm[8 * 64];
    __shared__ float satt[8 * 8];

    // Wc -> smem (16 KB, L2-hot after first block touches it)
    const float4* Wv = reinterpret_cast<const float4*>(Wc);
    #pragma unroll
    for (int i = 0; i < 4; i++)
        reinterpret_cast<float4*>(sW)[tid + i * 256] = Wv[tid + i * 256];

    // k[c][t] = sum over 8 partials (L2-hot: 1 MB of g_part)
    #pragma unroll
    for (int e = tid; e < 512; e += 256) {
        int c = e >> 6, t = e & 63;
        const float* gp = g_part + ((long)(b * Cc + c) * NSPLIT) * Tt + t;
        float s = 0.f;
        #pragma unroll
        for (int p = 0; p < NSPLIT; p++) s += gp[p * Tt];
        sk[e] = s;
    }
    __syncthreads();

    // m[c][s] = sum_t k[c][t] * Wc[t][s]
    #pragma unroll
    for (int e = tid; e < 512; e += 256) {
        int c = e >> 6, s = e & 63;
        float acc = 0.f;
        #pragma unroll
        for (int t = 0; t < 64; t++) acc += sk[c * 64 + t] * sW[t * 64 + s];
        sm[e] = acc;
    }
    __syncthreads();

    // scores[c][d] = sum_s m[c][s] * k[d][s]
    if (tid < 64) {
        int c = tid >> 3, d = tid & 7;
        float sc = 0.f;
        #pragma unroll
        for (int s = 0; s < 64; s++) sc += sm[c * 64 + s] * sk[d * 64 + s];
        satt[tid] = sc;
    }
    __syncthreads();

    // softmax over d per row c
    if (tid < 8) {
        float mx = -1e30f;
        #pragma unroll
        for (int j = 0; j < 8; j++) mx = fmaxf(mx, satt[tid * 8 + j]);
        float e[8], sum = 0.f;
        #pragma unroll
        for (int j = 0; j < 8; j++) { e[j] = __expf(satt[tid * 8 + j] - mx); sum += e[j]; }
        float inv = 1.f / sum;
        #pragma unroll
        for (int j = 0; j < 8; j++) satt[tid * 8 + j] = e[j] * inv;
    }
    __syncthreads();

    // main aggregation: x from L2 (evict-first), streaming stores
    int p = chunk * 256 + tid;
    const float4* xb = reinterpret_cast<const float4*>(x + (long)b * Cc * Nn * Tt);
    float4*       ob = reinterpret_cast<float4*>(out + (long)b * Cc * Nn * Tt);

    float4 acc[8];
    #pragma unroll
    for (int c = 0; c < 8; c++) acc[c] = make_float4(0.f, 0.f, 0.f, 0.f);

    #pragma unroll
    for (int i = 0; i < 8; i++) {
        float4 v = __ldcs(&xb[(long)i * NT4 + p]);   // L2 hit, evict-first (last use)
        #pragma unroll
        for (int c = 0; c < 8; c++) {
            float a = satt[c * 8 + i];
            acc[c].x += a * v.x; acc[c].y += a * v.y;
            acc[c].z += a * v.z; acc[c].w += a * v.w;
        }
    }
    #pragma unroll
    for (int c = 0; c < 8; c++)
        __stcs(&ob[(long)c * NT4 + p], acc[c]);      // evict-first: protect x[g] in L2
}

// ---------------------------------------------------------------------------
extern "C" void kernel_launch(void* const* d_in, const int* in_sizes, int n_in,
                              void* d_out, int out_size) {
    const float* x     = (const float*)d_in[0];
    const float* Wc    = (const float*)d_in[1];
    const float* alpha = (const float*)d_in[2];
    float* out = (float*)d_out;

    for (int g = 0; g < GROUPS; g++) {
        k_reduce<<<RED_BLOCKS, 256>>>(x, alpha, g);
        k_agg<<<AGG_BLOCKS, 256>>>(x, Wc, out, g);
    }
}

// round 4
// speedup vs baseline: 1.0035x; 1.0035x over previous
#include <cuda_runtime.h>
#include <math.h>

#define Bb 64
#define Cc 8
#define Nn 2048
#define Tt 64
#define NSPLIT 8
#define BPG 16                              // batches per group: x[g] = 64 MB < L2
#define GROUPS (Bb / BPG)                   // 4
#define RED_BLOCKS (BPG * Cc * NSPLIT)      // 1024
#define AGG_BLOCKS (BPG * 128)              // 2048
#define NT4 (Nn * Tt / 4)                   // 32768 float4 per (b,c)

// atomic-free reduction partials: [b*Cc+c][split][t]  (1 MB)
__device__ float g_part[Bb * Cc * NSPLIT * Tt];

// ---------------------------------------------------------------------------
// Phase 1: k partials for group g. Pure DRAM read stream; plants x[g] in L2.
// 1024 blocks x 256 threads. Block = one (b,c,split): 256 n-rows.
// ---------------------------------------------------------------------------
__global__ void __launch_bounds__(256)
k_reduce(const float* __restrict__ x, const float* __restrict__ alpha, int g) {
    int r     = blockIdx.x;
    int bcl   = r >> 3;                     // 0..127  (local b*8 + c)
    int split = r & 7;
    int b     = g * BPG + (bcl >> 3);
    int c     = bcl & 7;
    const float* xp = x + ((long)(b * Cc + c)) * Nn * Tt;

    __shared__ float s_alpha[256];
    __shared__ float4 s_red[256];

    int tid = threadIdx.x;
    s_alpha[tid] = alpha[split * 256 + tid];
    __syncthreads();

    int t4 = tid & 15, row = tid >> 4;
    int nbase = split * 256;
    float4 acc = make_float4(0.f, 0.f, 0.f, 0.f);
    #pragma unroll
    for (int i = 0; i < 16; i++) {
        int nl = row + i * 16;
        float4 v = reinterpret_cast<const float4*>(xp + (long)(nbase + nl) * Tt)[t4];
        float a = s_alpha[nl];
        acc.x += v.x * a; acc.y += v.y * a;
        acc.z += v.z * a; acc.w += v.w * a;
    }

    s_red[tid] = acc;
    __syncthreads();
    #pragma unroll
    for (int off = 8; off >= 1; off >>= 1) {
        if (row < off) {
            float4 o = s_red[(row + off) * 16 + t4];
            acc.x += o.x; acc.y += o.y; acc.z += o.z; acc.w += o.w;
            s_red[tid] = acc;
        }
        __syncthreads();
    }
    if (row == 0)
        reinterpret_cast<float4*>(
            g_part + ((long)(b * Cc + c) * NSPLIT + split) * Tt)[t4] = acc;
}

// ---------------------------------------------------------------------------
// Phase 2: aggregate group g. x[g] read from L2 (evict-first), out streamed.
// 2048 blocks x 256 threads. att[b] recomputed per block (cheap, hidden).
// ---------------------------------------------------------------------------
__global__ void __launch_bounds__(256)
k_agg(const float* __restrict__ x, const float* __restrict__ Wc,
      float* __restrict__ out, int g) {
    int bl    = blockIdx.x >> 7;            // 0..15
    int chunk = blockIdx.x & 127;
    int b     = g * BPG + bl;
    int tid   = threadIdx.x;

    __shared__ float sW[64 * 64];
    __shared__ float sk[8 * 64];
    __shared__ float sm[8 * 64];
    __shared__ float satt[8 * 8];

    // Wc -> smem (16 KB, L2-hot after first block touches it)
    const float4* Wv = reinterpret_cast<const float4*>(Wc);
    #pragma unroll
    for (int i = 0; i < 4; i++)
        reinterpret_cast<float4*>(sW)[tid + i * 256] = Wv[tid + i * 256];

    // k[c][t] = sum over 8 partials (L2-hot: 1 MB of g_part)
    #pragma unroll
    for (int e = tid; e < 512; e += 256) {
        int c = e >> 6, t = e & 63;
        const float* gp = g_part + ((long)(b * Cc + c) * NSPLIT) * Tt + t;
        float s = 0.f;
        #pragma unroll
        for (int p = 0; p < NSPLIT; p++) s += gp[p * Tt];
        sk[e] = s;
    }
    __syncthreads();

    // m[c][s] = sum_t k[c][t] * Wc[t][s]
    #pragma unroll
    for (int e = tid; e < 512; e += 256) {
        int c = e >> 6, s = e & 63;
        float acc = 0.f;
        #pragma unroll
        for (int t = 0; t < 64; t++) acc += sk[c * 64 + t] * sW[t * 64 + s];
        sm[e] = acc;
    }
    __syncthreads();

    // scores[c][d] = sum_s m[c][s] * k[d][s]
    if (tid < 64) {
        int c = tid >> 3, d = tid & 7;
        float sc = 0.f;
        #pragma unroll
        for (int s = 0; s < 64; s++) sc += sm[c * 64 + s] * sk[d * 64 + s];
        satt[tid] = sc;
    }
    __syncthreads();

    // softmax over d per row c
    if (tid < 8) {
        float mx = -1e30f;
        #pragma unroll
        for (int j = 0; j < 8; j++) mx = fmaxf(mx, satt[tid * 8 + j]);
        float e[8], sum = 0.f;
        #pragma unroll
        for (int j = 0; j < 8; j++) { e[j] = __expf(satt[tid * 8 + j] - mx); sum += e[j]; }
        float inv = 1.f / sum;
        #pragma unroll
        for (int j = 0; j < 8; j++) satt[tid * 8 + j] = e[j] * inv;
    }
    __syncthreads();

    // main aggregation: x from L2 (evict-first), streaming stores
    int p = chunk * 256 + tid;
    const float4* xb = reinterpret_cast<const float4*>(x + (long)b * Cc * Nn * Tt);
    float4*       ob = reinterpret_cast<float4*>(out + (long)b * Cc * Nn * Tt);

    float4 acc[8];
    #pragma unroll
    for (int c = 0; c < 8; c++) acc[c] = make_float4(0.f, 0.f, 0.f, 0.f);

    #pragma unroll
    for (int i = 0; i < 8; i++) {
        float4 v = __ldcs(&xb[(long)i * NT4 + p]);   // L2 hit, evict-first (last use)
        #pragma unroll
        for (int c = 0; c < 8; c++) {
            float a = satt[c * 8 + i];
            acc[c].x += a * v.x; acc[c].y += a * v.y;
            acc[c].z += a * v.z; acc[c].w += a * v.w;
        }
    }
    #pragma unroll
    for (int c = 0; c < 8; c++)
        __stcs(&ob[(long)c * NT4 + p], acc[c]);      // evict-first: protect x[g] in L2
}

// ---------------------------------------------------------------------------
extern "C" void kernel_launch(void* const* d_in, const int* in_sizes, int n_in,
                              void* d_out, int out_size) {
    const float* x     = (const float*)d_in[0];
    const float* Wc    = (const float*)d_in[1];
    const float* alpha = (const float*)d_in[2];
    float* out = (float*)d_out;

    for (int g = 0; g < GROUPS; g++) {
        k_reduce<<<RED_BLOCKS, 256>>>(x, alpha, g);
        k_agg<<<AGG_BLOCKS, 256>>>(x, Wc, out, g);
    }
}

// round 5
// speedup vs baseline: 1.1358x; 1.1318x over previous
#include <cuda_runtime.h>
#include <math.h>

#define Bb 64
#define Cc 8
#define Nn 2048
#define Tt 64
#define NSPLIT 8
#define BPG 16                              // batches per group: x[g] = 64 MB < L2
#define GROUPS (Bb / BPG)                   // 4
#define RED_BLOCKS (BPG * Cc * NSPLIT)      // 1024
#define AGG_BLOCKS (BPG * 128)              // 2048
#define NT4 (Nn * Tt / 4)                   // 32768 float4 per (b,c)

// scratch
__device__ float g_part[Bb * Cc * NSPLIT * Tt];   // reduction partials (1 MB)
__device__ float g_att[Bb * Cc * Cc];             // attention weights

// ---------------------------------------------------------------------------
// Phase 1: k partials for group g. Pure DRAM read stream; plants x[g] in L2.
// ---------------------------------------------------------------------------
__global__ void __launch_bounds__(256)
k_reduce(const float* __restrict__ x, const float* __restrict__ alpha, int g) {
    int r     = blockIdx.x;
    int bcl   = r >> 3;                     // local b*8 + c
    int split = r & 7;
    int b     = g * BPG + (bcl >> 3);
    int c     = bcl & 7;
    const float* xp = x + ((long)(b * Cc + c)) * Nn * Tt;

    __shared__ float s_alpha[256];
    __shared__ float4 s_red[256];

    int tid = threadIdx.x;
    s_alpha[tid] = alpha[split * 256 + tid];
    __syncthreads();

    int t4 = tid & 15, row = tid >> 4;
    int nbase = split * 256;
    float4 acc = make_float4(0.f, 0.f, 0.f, 0.f);
    #pragma unroll
    for (int i = 0; i < 16; i++) {
        int nl = row + i * 16;
        float4 v = reinterpret_cast<const float4*>(xp + (long)(nbase + nl) * Tt)[t4];
        float a = s_alpha[nl];
        acc.x += v.x * a; acc.y += v.y * a;
        acc.z += v.z * a; acc.w += v.w * a;
    }

    s_red[tid] = acc;
    __syncthreads();
    #pragma unroll
    for (int off = 8; off >= 1; off >>= 1) {
        if (row < off) {
            float4 o = s_red[(row + off) * 16 + t4];
            acc.x += o.x; acc.y += o.y; acc.z += o.z; acc.w += o.w;
            s_red[tid] = acc;
        }
        __syncthreads();
    }
    if (row == 0)
        reinterpret_cast<float4*>(
            g_part + ((long)(b * Cc + c) * NSPLIT + split) * Tt)[t4] = acc;
}

// ---------------------------------------------------------------------------
// Phase 2: att[b] for group g. 16 blocks x 64 threads, trivial cost.
// ---------------------------------------------------------------------------
__global__ void __launch_bounds__(64)
k_att(const float* __restrict__ Wc, int g) {
    int b = g * BPG + blockIdx.x;
    int tid = threadIdx.x;                  // 0..63

    __shared__ float sW[64 * 64];
    __shared__ float sk[8 * 64];
    __shared__ float sm[8 * 64];
    __shared__ float ssc[8 * 8];

    for (int i = tid; i < 64 * 64; i += 64) sW[i] = Wc[i];
    for (int i = tid; i < 8 * 64; i += 64) {
        int c = i >> 6, t = i & 63;
        const float* gp = g_part + ((long)(b * Cc + c) * NSPLIT) * Tt + t;
        float s = 0.f;
        #pragma unroll
        for (int p = 0; p < NSPLIT; p++) s += gp[p * Tt];
        sk[i] = s;
    }
    __syncthreads();

    // m[c][s] = sum_t k[c][t] * Wc[t][s]
    #pragma unroll
    for (int c = 0; c < 8; c++) {
        float acc = 0.f;
        #pragma unroll
        for (int t = 0; t < 64; t++) acc += sk[c * 64 + t] * sW[t * 64 + tid];
        sm[c * 64 + tid] = acc;
    }
    __syncthreads();

    // scores[c][d]
    int c = tid >> 3, d = tid & 7;
    float sc = 0.f;
    #pragma unroll
    for (int s = 0; s < 64; s++) sc += sm[c * 64 + s] * sk[d * 64 + s];
    ssc[tid] = sc;
    __syncthreads();

    if (tid < 8) {
        float mx = -1e30f;
        #pragma unroll
        for (int j = 0; j < 8; j++) mx = fmaxf(mx, ssc[tid * 8 + j]);
        float e[8], sum = 0.f;
        #pragma unroll
        for (int j = 0; j < 8; j++) { e[j] = __expf(ssc[tid * 8 + j] - mx); sum += e[j]; }
        float inv = 1.f / sum;
        #pragma unroll
        for (int j = 0; j < 8; j++)
            g_att[b * Cc * Cc + tid * Cc + j] = e[j] * inv;
    }
}

// ---------------------------------------------------------------------------
// Phase 3: aggregate group g. Lean: x from L2 (evict-first), streaming stores.
// ---------------------------------------------------------------------------
__global__ void __launch_bounds__(256)
k_agg(const float* __restrict__ x, float* __restrict__ out, int g) {
    int bl    = blockIdx.x >> 7;            // 0..15
    int chunk = blockIdx.x & 127;
    int b     = g * BPG + bl;
    int tid   = threadIdx.x;

    __shared__ float satt[64];
    if (tid < 64) satt[tid] = g_att[b * 64 + tid];
    __syncthreads();

    int p = chunk * 256 + tid;
    const float4* xb = reinterpret_cast<const float4*>(x + (long)b * Cc * Nn * Tt);
    float4*       ob = reinterpret_cast<float4*>(out + (long)b * Cc * Nn * Tt);

    float4 acc[8];
    #pragma unroll
    for (int c = 0; c < 8; c++) acc[c] = make_float4(0.f, 0.f, 0.f, 0.f);

    #pragma unroll
    for (int i = 0; i < 8; i++) {
        float4 v = __ldcs(&xb[(long)i * NT4 + p]);   // L2 hit, evict-first (last use)
        #pragma unroll
        for (int c = 0; c < 8; c++) {
            float a = satt[c * 8 + i];
            acc[c].x += a * v.x; acc[c].y += a * v.y;
            acc[c].z += a * v.z; acc[c].w += a * v.w;
        }
    }
    #pragma unroll
    for (int c = 0; c < 8; c++)
        __stcs(&ob[(long)c * NT4 + p], acc[c]);      // evict-first: protect x[g] in L2
}

// ---------------------------------------------------------------------------
extern "C" void kernel_launch(void* const* d_in, const int* in_sizes, int n_in,
                              void* d_out, int out_size) {
    const float* x     = (const float*)d_in[0];
    const float* Wc    = (const float*)d_in[1];
    const float* alpha = (const float*)d_in[2];
    float* out = (float*)d_out;

    for (int g = 0; g < GROUPS; g++) {
        k_reduce<<<RED_BLOCKS, 256>>>(x, alpha, g);
        k_att<<<BPG, 64>>>(Wc, g);
        k_agg<<<AGG_BLOCKS, 256>>>(x, out, g);
    }
}

// round 6
// speedup vs baseline: 1.2567x; 1.1064x over previous
#include <cuda_runtime.h>
#include <math.h>

#define Bb 64
#define Cc 8
#define Nn 2048
#define Tt 64
#define NSPLIT 8
#define BPG 16                              // batches per group: x[g] = 64 MB < L2
#define GROUPS (Bb / BPG)                   // 4
#define RED_BLOCKS (BPG * Cc * NSPLIT)      // 1024
#define AGG_BLOCKS (BPG * 128)              // 2048
#define NT4 (Nn * Tt / 4)                   // 32768 float4 per (b,c)

// scratch
__device__ float g_part[Bb * Cc * NSPLIT * Tt];   // reduction partials (1 MB)
__device__ float g_att[Bb * Cc * Cc];             // attention weights

// ---------------------------------------------------------------------------
// Phase 1: k partials for group g. Pure DRAM read stream; plants x[g] in L2.
// Launched as PDL secondary: overlaps the preceding agg's write stream.
// ---------------------------------------------------------------------------
__global__ void __launch_bounds__(256)
k_reduce(const float* __restrict__ x, const float* __restrict__ alpha, int g) {
    int r     = blockIdx.x;
    int bcl   = r >> 3;                     // local b*8 + c
    int split = r & 7;
    int b     = g * BPG + (bcl >> 3);
    int c     = bcl & 7;
    const float* xp = x + ((long)(b * Cc + c)) * Nn * Tt;

    __shared__ float s_alpha[256];
    __shared__ float4 s_red[256];

    int tid = threadIdx.x;
    s_alpha[tid] = alpha[split * 256 + tid];
    __syncthreads();

    int t4 = tid & 15, row = tid >> 4;
    int nbase = split * 256;
    float4 acc = make_float4(0.f, 0.f, 0.f, 0.f);
    #pragma unroll
    for (int i = 0; i < 16; i++) {
        int nl = row + i * 16;
        float4 v = reinterpret_cast<const float4*>(xp + (long)(nbase + nl) * Tt)[t4];
        float a = s_alpha[nl];
        acc.x += v.x * a; acc.y += v.y * a;
        acc.z += v.z * a; acc.w += v.w * a;
    }

    s_red[tid] = acc;
    __syncthreads();
    #pragma unroll
    for (int off = 8; off >= 1; off >>= 1) {
        if (row < off) {
            float4 o = s_red[(row + off) * 16 + t4];
            acc.x += o.x; acc.y += o.y; acc.z += o.z; acc.w += o.w;
            s_red[tid] = acc;
        }
        __syncthreads();
    }
    if (row == 0)
        reinterpret_cast<float4*>(
            g_part + ((long)(b * Cc + c) * NSPLIT + split) * Tt)[t4] = acc;
}

// ---------------------------------------------------------------------------
// Phase 2: att[b] for group g. Tiny.
// ---------------------------------------------------------------------------
__global__ void __launch_bounds__(64)
k_att(const float* __restrict__ Wc, int g) {
    int b = g * BPG + blockIdx.x;
    int tid = threadIdx.x;                  // 0..63

    __shared__ float sW[64 * 64];
    __shared__ float sk[8 * 64];
    __shared__ float sm[8 * 64];
    __shared__ float ssc[8 * 8];

    for (int i = tid; i < 64 * 64; i += 64) sW[i] = Wc[i];
    for (int i = tid; i < 8 * 64; i += 64) {
        int c = i >> 6, t = i & 63;
        const float* gp = g_part + ((long)(b * Cc + c) * NSPLIT) * Tt + t;
        float s = 0.f;
        #pragma unroll
        for (int p = 0; p < NSPLIT; p++) s += gp[p * Tt];
        sk[i] = s;
    }
    __syncthreads();

    #pragma unroll
    for (int c = 0; c < 8; c++) {
        float acc = 0.f;
        #pragma unroll
        for (int t = 0; t < 64; t++) acc += sk[c * 64 + t] * sW[t * 64 + tid];
        sm[c * 64 + tid] = acc;
    }
    __syncthreads();

    int c = tid >> 3, d = tid & 7;
    float sc = 0.f;
    #pragma unroll
    for (int s = 0; s < 64; s++) sc += sm[c * 64 + s] * sk[d * 64 + s];
    ssc[tid] = sc;
    __syncthreads();

    if (tid < 8) {
        float mx = -1e30f;
        #pragma unroll
        for (int j = 0; j < 8; j++) mx = fmaxf(mx, ssc[tid * 8 + j]);
        float e[8], sum = 0.f;
        #pragma unroll
        for (int j = 0; j < 8; j++) { e[j] = __expf(ssc[tid * 8 + j] - mx); sum += e[j]; }
        float inv = 1.f / sum;
        #pragma unroll
        for (int j = 0; j < 8; j++)
            g_att[b * Cc * Cc + tid * Cc + j] = e[j] * inv;
    }
}

// ---------------------------------------------------------------------------
// Phase 3: aggregate group g. x from L2 (evict-first), streaming stores.
// Triggers PDL completion immediately so the next group's reduce overlaps.
// ---------------------------------------------------------------------------
__global__ void __launch_bounds__(256)
k_agg(const float* __restrict__ x, float* __restrict__ out, int g) {
#if __CUDA_ARCH__ >= 900
    cudaTriggerProgrammaticLaunchCompletion();
#endif
    int bl    = blockIdx.x >> 7;            // 0..15
    int chunk = blockIdx.x & 127;
    int b     = g * BPG + bl;
    int tid   = threadIdx.x;

    __shared__ float satt[64];
    if (tid < 64) satt[tid] = g_att[b * 64 + tid];
    __syncthreads();

    int p = chunk * 256 + tid;
    const float4* xb = reinterpret_cast<const float4*>(x + (long)b * Cc * Nn * Tt);
    float4*       ob = reinterpret_cast<float4*>(out + (long)b * Cc * Nn * Tt);

    // prefetch all 8 channel vectors (MLP = 8)
    float4 v[8];
    #pragma unroll
    for (int i = 0; i < 8; i++)
        v[i] = __ldcs(&xb[(long)i * NT4 + p]);   // L2 hit, evict-first (last use)

    float4 acc[8];
    #pragma unroll
    for (int c = 0; c < 8; c++) {
        acc[c] = make_float4(0.f, 0.f, 0.f, 0.f);
        #pragma unroll
        for (int i = 0; i < 8; i++) {
            float a = satt[c * 8 + i];
            acc[c].x += a * v[i].x; acc[c].y += a * v[i].y;
            acc[c].z += a * v[i].z; acc[c].w += a * v[i].w;
        }
        __stcs(&ob[(long)c * NT4 + p], acc[c]);  // evict-first: protect x in L2
    }
}

// ---------------------------------------------------------------------------
extern "C" void kernel_launch(void* const* d_in, const int* in_sizes, int n_in,
                              void* d_out, int out_size) {
    const float* x     = (const float*)d_in[0];
    const float* Wc    = (const float*)d_in[1];
    const float* alpha = (const float*)d_in[2];
    float* out = (float*)d_out;

    // reduce(0), att(0) up front
    k_reduce<<<RED_BLOCKS, 256>>>(x, alpha, 0);
    k_att<<<BPG, 64>>>(Wc, 0);

    cudaLaunchAttribute attr[1];
    attr[0].id = cudaLaunchAttributeProgrammaticStreamSerialization;
    attr[0].val.programmaticStreamSerializationAllowed = 1;

    for (int g = 0; g < GROUPS; g++) {
        // agg(g): primary, triggers early
        k_agg<<<AGG_BLOCKS, 256>>>(x, out, g);

        if (g + 1 < GROUPS) {
            // reduce(g+1): PDL secondary — overlaps agg(g)
            cudaLaunchConfig_t cfg = {};
            cfg.gridDim = dim3(RED_BLOCKS);
            cfg.blockDim = dim3(256);
            cfg.dynamicSmemBytes = 0;
            cfg.stream = 0;
            cfg.attrs = attr;
            cfg.numAttrs = 1;
            cudaLaunchKernelEx(&cfg, k_reduce, x, alpha, g + 1);
            // att(g+1): normal launch — waits reduce(g+1) AND agg(g)
            k_att<<<BPG, 64>>>(Wc, g + 1);
        }
    }
}